// round 4
// baseline (speedup 1.0000x reference)
#include <cuda_runtime.h>
#include <cuda_bf16.h>
#include <math.h>

// Problem constants
#define B_DIM 16
#define S_DIM 4096
#define F_DIM 512
#define NCLS 10
#define HID 64
#define ODIM 128

#define COLS_PER_CTA 4
#define NTHREADS 512
#define TAB_SLOTS 8192          // per-column hash slots (<=4096 distinct -> LF 0.5)
#define EMPTY_SLOT 0xFFFFFFFFu  // canonicalized values are never this bit pattern

// Shared memory layout (dynamic), bytes:
// [0, 131072)        phase 1: 4 hash tables of 8192 u32
//                    phase 2 overlay: red[16][25] @0 | binred[40] @2048 |
//                                     stats6 @4096 | h @4608 | w2s @8192 (32KB)
// [131072, 212992)   per-thread class bins: 512 threads x 10 classes x 4 cols f32
#define OFF_TABLES   0
#define OFF_BINS     131072
#define OFF_RED      0
#define OFF_BINRED   2048
#define OFF_STATS    4096
#define OFF_H        4608
#define OFF_W2       8192
#define SMEM_BYTES   212992

typedef unsigned long long ull;

#define ADD2(d,a,b)   asm("add.rn.f32x2 %0, %1, %2;"      : "=l"(d) : "l"(a), "l"(b))
#define FMA2(d,a,b,c) asm("fma.rn.f32x2 %0, %1, %2, %3;"  : "=l"(d) : "l"(a), "l"(b), "l"(c))

__device__ __forceinline__ ull pk2(float lo, float hi) {
    ull r; asm("mov.b64 %0, {%1, %2};" : "=l"(r) : "f"(lo), "f"(hi)); return r;
}
__device__ __forceinline__ void upk2(ull v, float& lo, float& hi) {
    asm("mov.b64 {%0, %1}, %2;" : "=f"(lo), "=f"(hi) : "l"(v));
}

__device__ float g_class_counts[B_DIM * NCLS];

__global__ void class_count_kernel(const int* __restrict__ y) {
    __shared__ int hist[NCLS];
    int b = blockIdx.x;
    if (threadIdx.x < NCLS) hist[threadIdx.x] = 0;
    __syncthreads();
    for (int i = threadIdx.x; i < S_DIM; i += blockDim.x)
        atomicAdd(&hist[y[b * S_DIM + i]], 1);
    __syncthreads();
    if (threadIdx.x < NCLS) g_class_counts[b * NCLS + threadIdx.x] = (float)hist[threadIdx.x];
}

// Exact distinct insert: Fibonacci hash, CAS-first, linear probe on the rare path.
// Total unique count is the number of CAS winners -> race-order invariant.
__device__ __forceinline__ void hins(unsigned int* __restrict__ tab, float v, float& uniq) {
    unsigned int bits = __float_as_uint(v);
    bits = (v == 0.0f) ? 0u : bits;                 // -0 -> +0 canonicalization
    unsigned int slot = (bits * 2654435761u) >> 19; // top 13 bits of low product
    unsigned int cur = atomicCAS(tab + slot, EMPTY_SLOT, bits);
    while (cur != EMPTY_SLOT && cur != bits) {      // occupied by a different value
        slot = (slot + 1) & (TAB_SLOTS - 1);
        cur = atomicCAS(tab + slot, EMPTY_SLOT, bits);
    }
    if (cur == EMPTY_SLOT) uniq += 1.0f;
}

__global__ __launch_bounds__(NTHREADS, 1)
void stats_mlp_kernel(const float* __restrict__ X,
                      const int*   __restrict__ y,
                      const float* __restrict__ w1,
                      const float* __restrict__ b1,
                      const float* __restrict__ w2,
                      const float* __restrict__ b2,
                      float* __restrict__ out) {
    extern __shared__ char smem[];
    unsigned int* tables = (unsigned int*)(smem + OFF_TABLES);
    float* bins = (float*)(smem + OFF_BINS);

    const int tid  = threadIdx.x;
    const int lane = tid & 31;
    const int wid  = tid >> 5;
    const int g = blockIdx.x;        // feature group 0..127
    const int b = blockIdx.y;        // batch 0..15
    const int f0 = g * COLS_PER_CTA;

    // init tables (32768 u32) and this thread's 40 class bins
    {
        uint4* tv = (uint4*)tables;
        uint4 e = make_uint4(EMPTY_SLOT, EMPTY_SLOT, EMPTY_SLOT, EMPTY_SLOT);
        #pragma unroll
        for (int i = 0; i < (COLS_PER_CTA * TAB_SLOTS / 4) / NTHREADS; i++)
            tv[tid + i * NTHREADS] = e;
        float4* bz = (float4*)(bins + tid * 40);
        float4 z = make_float4(0.f, 0.f, 0.f, 0.f);
        #pragma unroll
        for (int i = 0; i < 10; i++) bz[i] = z;
    }
    __syncthreads();

    unsigned int* t0 = tables;
    unsigned int* t1 = tables + TAB_SLOTS;
    unsigned int* t2 = tables + 2 * TAB_SLOTS;
    unsigned int* t3 = tables + 3 * TAB_SLOTS;

    // packed accumulators
    ull sum01 = 0, sum23 = 0, sq01 = 0, sq23 = 0;
    float sabs0 = 0, sabs1 = 0, sabs2 = 0, sabs3 = 0;
    float mabs0 = 0, mabs1 = 0, mabs2 = 0, mabs3 = 0;
    float nanc0 = 0, nanc1 = 0, nanc2 = 0, nanc3 = 0;
    float uq0 = 0, uq1 = 0, uq2 = 0, uq3 = 0;

    const float4* Xr = (const float4*)(X + (size_t)b * S_DIM * F_DIM + f0);
    const int* yb = y + b * S_DIM;

    #pragma unroll
    for (int i = 0; i < S_DIM / NTHREADS; i++) {
        const int r = tid + NTHREADS * i;
        float4 x = __ldg(&Xr[(size_t)r * (F_DIM / 4)]);
        int yv = __ldg(&yb[r]);

        bool k0 = (x.x == x.x), k1 = (x.y == x.y), k2 = (x.z == x.z), k3 = (x.w == x.w);
        float v0 = k0 ? x.x : 0.f; if (!k0) nanc0 += 1.f;
        float v1 = k1 ? x.y : 0.f; if (!k1) nanc1 += 1.f;
        float v2 = k2 ? x.z : 0.f; if (!k2) nanc2 += 1.f;
        float v3 = k3 ? x.w : 0.f; if (!k3) nanc3 += 1.f;

        ull v01 = pk2(v0, v1), v23 = pk2(v2, v3);
        ADD2(sum01, sum01, v01); ADD2(sum23, sum23, v23);
        FMA2(sq01, v01, v01, sq01); FMA2(sq23, v23, v23, sq23);
        sabs0 += fabsf(v0); sabs1 += fabsf(v1); sabs2 += fabsf(v2); sabs3 += fabsf(v3);
        mabs0 = fmaxf(mabs0, fabsf(v0)); mabs1 = fmaxf(mabs1, fabsf(v1));
        mabs2 = fmaxf(mabs2, fabsf(v2)); mabs3 = fmaxf(mabs3, fabsf(v3));

        // class bins: private per thread, y-indexed, one LDS.128/STS.128
        ulonglong2* bp = (ulonglong2*)(bins + tid * 40 + yv * 4);
        ulonglong2 cc = *bp;
        ADD2(cc.x, cc.x, v01); ADD2(cc.y, cc.y, v23);
        *bp = cc;

        hins(t0, v0, uq0); hins(t1, v1, uq1); hins(t2, v2, uq2); hins(t3, v3, uq3);
    }
    __syncthreads();   // tables & bins final; tables region now reusable as overlay

    float* red    = (float*)(smem + OFF_RED);     // [16][25]
    float* binred = (float*)(smem + OFF_BINRED);  // [40]
    float* stats6 = (float*)(smem + OFF_STATS);
    float* hsm    = (float*)(smem + OFF_H);
    float* w2s    = (float*)(smem + OFF_W2);

    // 1) warp butterfly reduce the 24 base stats
    {
        float st[24];
        upk2(sum01, st[0], st[1]); upk2(sum23, st[2], st[3]);
        upk2(sq01, st[4], st[5]);  upk2(sq23, st[6], st[7]);
        st[8] = sabs0; st[9] = sabs1; st[10] = sabs2; st[11] = sabs3;
        st[12] = mabs0; st[13] = mabs1; st[14] = mabs2; st[15] = mabs3;
        st[16] = nanc0; st[17] = nanc1; st[18] = nanc2; st[19] = nanc3;
        st[20] = uq0; st[21] = uq1; st[22] = uq2; st[23] = uq3;
        #pragma unroll
        for (int k = 0; k < 24; k++) {
            float v = st[k];
            #pragma unroll
            for (int off = 16; off > 0; off >>= 1) {
                float o = __shfl_xor_sync(0xFFFFFFFFu, v, off);
                v = (k >= 12 && k < 16) ? fmaxf(v, o) : v + o;
            }
            st[k] = v;
        }
        if (lane == 0) {
            #pragma unroll
            for (int k = 0; k < 24; k++) red[wid * 25 + k] = st[k];
        }
    }

    // 2) reduce class bins (512 threads x 40) -> 40 totals, warp-parallel
    for (int k = wid; k < 40; k += 16) {       // k = cls*4 + col
        float s = 0.f;
        #pragma unroll
        for (int j = 0; j < 16; j++) s += bins[(lane + 32 * j) * 40 + k];
        #pragma unroll
        for (int off = 16; off > 0; off >>= 1)
            s += __shfl_xor_sync(0xFFFFFFFFu, s, off);
        if (lane == 0) binred[k] = s;
    }

    // stage w2 into smem
    {
        const float4* w2v = (const float4*)w2;
        float4* w2d = (float4*)w2s;
        #pragma unroll
        for (int i = 0; i < (HID * ODIM / 4) / NTHREADS; i++)
            w2d[tid + i * NTHREADS] = w2v[tid + i * NTHREADS];
    }
    __syncthreads();

    // 3) per-column final stats (threads 0..3)
    if (tid < COLS_PER_CTA) {
        const float Sf = (float)S_DIM;
        float tsum = 0, tsq = 0, tsabs = 0, tmabs = 0, tnan = 0, tuniq = 0;
        #pragma unroll
        for (int w = 0; w < 16; w++) {
            tsum  += red[w * 25 + 0 + tid];
            tsq   += red[w * 25 + 4 + tid];
            tsabs += red[w * 25 + 8 + tid];
            tmabs  = fmaxf(tmabs, red[w * 25 + 12 + tid]);
            tnan  += red[w * 25 + 16 + tid];
            tuniq += red[w * 25 + 20 + tid];
        }
        float gmean = tsum / Sf;
        float var = fmaxf(tsq / Sf - gmean * gmean, 0.0f);
        float between = 0.0f;
        #pragma unroll
        for (int c = 0; c < NCLS; c++) {
            float cnt = g_class_counts[b * NCLS + c];
            float cm = binred[c * 4 + tid] / fmaxf(cnt, 1.0f);
            float d = cm - gmean;
            between = fmaf(cnt, d * d, between);
        }
        between /= Sf;
        stats6[tid * 6 + 0] = between / fmaxf(var, 1e-6f);
        stats6[tid * 6 + 1] = tnan / Sf;
        stats6[tid * 6 + 2] = tuniq / Sf;
        stats6[tid * 6 + 3] = var;
        stats6[tid * 6 + 4] = tsabs / Sf;
        stats6[tid * 6 + 5] = tmabs;
    }
    __syncthreads();

    // 4) MLP layer 1: h = gelu_exact(stats6 @ w1 + b1)
    if (tid < COLS_PER_CTA * HID) {
        int ch = tid >> 6, j = tid & 63;
        float acc = b1[j];
        #pragma unroll
        for (int i = 0; i < 6; i++)
            acc = fmaf(stats6[ch * 6 + i], w1[i * HID + j], acc);
        hsm[ch * HID + j] = 0.5f * acc * (1.0f + erff(acc * 0.70710678118654752f));
    }
    __syncthreads();

    // 5) MLP layer 2: out = h @ w2 + b2 (one output element per thread)
    {
        int ch = tid >> 7, k = tid & 127;
        float acc = b2[k];
        #pragma unroll
        for (int j = 0; j < HID; j++)
            acc = fmaf(hsm[ch * HID + j], w2s[j * ODIM + k], acc);
        out[(((size_t)b * F_DIM) + f0 + ch) * ODIM + k] = acc;
    }
}

extern "C" void kernel_launch(void* const* d_in, const int* in_sizes, int n_in,
                              void* d_out, int out_size) {
    const float* X  = (const float*)d_in[0];
    const int*   y  = (const int*)d_in[1];
    const float* w1 = (const float*)d_in[2];
    const float* b1 = (const float*)d_in[3];
    const float* w2 = (const float*)d_in[4];
    const float* b2 = (const float*)d_in[5];
    float* out = (float*)d_out;

    cudaFuncSetAttribute(stats_mlp_kernel,
                         cudaFuncAttributeMaxDynamicSharedMemorySize, SMEM_BYTES);

    class_count_kernel<<<B_DIM, 256>>>(y);
    dim3 grid(F_DIM / COLS_PER_CTA, B_DIM);
    stats_mlp_kernel<<<grid, NTHREADS, SMEM_BYTES>>>(X, y, w1, b1, w2, b2, out);
}

// round 5
// speedup vs baseline: 2.5103x; 2.5103x over previous
#include <cuda_runtime.h>
#include <cuda_bf16.h>
#include <math.h>

// Problem constants
#define B_DIM 16
#define S_DIM 4096
#define F_DIM 512
#define NCLS 10
#define HID 64
#define ODIM 128

#define COLS_PER_CTA 4
#define NTHREADS 1024
#define ROWS_PER_THREAD (S_DIM / (NTHREADS / COLS_PER_CTA))   // 16
#define TAB_SLOTS 8192          // per-column hash slots (<=4096 distinct -> LF 0.5)
#define EMPTY_SLOT 0xFFFFFFFFu  // canonicalized values never have this bit pattern

// Shared memory layout (dynamic), bytes:
// phase 1: [0, 131072)       4 hash tables of 8192 u32
//          [131072, 147456)  y labels for this batch (4096 int)
// phase 2 overlay (inside the tables region, after __syncthreads):
//          [0, 69632)        reduction buffer 1024 x 17 floats
//          [69632, 69728)    stats6 (4 cols x 6)
//          [69888, 70912)    h buffer (4 cols x 64)
//          [71680, 104448)   w2 staged (64x128 floats)
#define OFF_TABLES   0
#define OFF_YBUF     131072
#define OFF_BUF      0
#define OFF_STATS    69632
#define OFF_H        69888
#define OFF_W2       71680
#define SMEM_BYTES   147456

__device__ float g_class_counts[B_DIM * NCLS];

__global__ void class_count_kernel(const int* __restrict__ y) {
    __shared__ int hist[NCLS];
    int b = blockIdx.x;
    if (threadIdx.x < NCLS) hist[threadIdx.x] = 0;
    __syncthreads();
    for (int i = threadIdx.x; i < S_DIM; i += blockDim.x)
        atomicAdd(&hist[y[b * S_DIM + i]], 1);
    __syncthreads();
    if (threadIdx.x < NCLS) g_class_counts[b * NCLS + threadIdx.x] = (float)hist[threadIdx.x];
}

// Exact distinct-count insert: Fibonacci hash, CAS-first (no pre-read on hot path),
// linear probe on the rare collision path. Unique total = number of CAS winners,
// which is race-order invariant -> deterministic.
__device__ __forceinline__ void hins(unsigned int* __restrict__ tab, float v, float& uniq) {
    unsigned int bits = __float_as_uint(v);
    bits = (v == 0.0f) ? 0u : bits;                 // -0 -> +0 canonicalization
    unsigned int slot = (bits * 2654435761u) >> 19; // top 13 bits
    unsigned int cur = atomicCAS(tab + slot, EMPTY_SLOT, bits);
    while (cur != EMPTY_SLOT && cur != bits) {
        slot = (slot + 1) & (TAB_SLOTS - 1);
        cur = atomicCAS(tab + slot, EMPTY_SLOT, bits);
    }
    if (cur == EMPTY_SLOT) uniq += 1.0f;
}

__global__ __launch_bounds__(NTHREADS, 1)
void stats_mlp_kernel(const float* __restrict__ X,
                      const int*   __restrict__ y,
                      const float* __restrict__ w1,
                      const float* __restrict__ b1,
                      const float* __restrict__ w2,
                      const float* __restrict__ b2,
                      float* __restrict__ out) {
    extern __shared__ char smem[];
    unsigned int* tables = (unsigned int*)(smem + OFF_TABLES);
    int* ybuf = (int*)(smem + OFF_YBUF);

    const int tid = threadIdx.x;
    const int g  = blockIdx.x;       // feature group 0..127
    const int b  = blockIdx.y;       // batch 0..15
    const int f0 = g * COLS_PER_CTA;

    // init hash tables (32768 words) with EMPTY (vectorized)
    {
        uint4* tv = (uint4*)tables;
        uint4 e = make_uint4(EMPTY_SLOT, EMPTY_SLOT, EMPTY_SLOT, EMPTY_SLOT);
        #pragma unroll
        for (int i = 0; i < (COLS_PER_CTA * TAB_SLOTS / 4) / NTHREADS; i++)
            tv[tid + i * NTHREADS] = e;
    }
    // stage y for this batch
    #pragma unroll
    for (int i = 0; i < S_DIM / NTHREADS; i++)
        ybuf[tid + i * NTHREADS] = y[b * S_DIM + tid + i * NTHREADS];
    __syncthreads();

    const int col = tid & 3;         // 4 consecutive lanes read consecutive floats
    const int r0  = tid >> 2;        // 0..255

    float sum = 0.f, sumsq = 0.f, sumabs = 0.f, maxabs = 0.f, nanc = 0.f;
    float uniq = 0.f;
    float csum[NCLS];
    #pragma unroll
    for (int c = 0; c < NCLS; c++) csum[c] = 0.f;

    unsigned int* tab = tables + col * TAB_SLOTS;
    const float* Xb = X + ((size_t)b * S_DIM) * F_DIM + f0 + col;

    #pragma unroll 4
    for (int i = 0; i < ROWS_PER_THREAD; i++) {
        const int r = r0 + 256 * i;
        float x = __ldg(&Xb[(size_t)r * F_DIM]);
        int yv = ybuf[r];
        bool isn = isnan(x);
        float v = isn ? 0.0f : x;
        nanc += isn ? 1.0f : 0.0f;
        sum += v;
        sumsq = fmaf(v, v, sumsq);
        float a = fabsf(v);
        sumabs += a;
        maxabs = fmaxf(maxabs, a);
        #pragma unroll
        for (int c = 0; c < NCLS; c++)
            csum[c] += (yv == c) ? v : 0.0f;

        hins(tab, v, uniq);
    }
    __syncthreads();   // tables & ybuf done; tables region reusable as overlay

    // ---- deterministic tree reduction: 16 stats per thread ----
    float* buf = (float*)(smem + OFF_BUF);
    {
        float st[16] = {sum, sumsq, sumabs, maxabs, nanc, uniq,
                        csum[0], csum[1], csum[2], csum[3], csum[4],
                        csum[5], csum[6], csum[7], csum[8], csum[9]};
        #pragma unroll
        for (int s = 0; s < 16; s++) buf[tid * 17 + s] = st[s];
    }
    __syncthreads();
    #pragma unroll
    for (int off = 512; off >= 4; off >>= 1) {  // off multiple of 4 keeps col alignment
        if (tid < off) {
            #pragma unroll
            for (int s = 0; s < 16; s++) {
                float o = buf[(tid + off) * 17 + s];
                if (s == 3) buf[tid * 17 + s] = fmaxf(buf[tid * 17 + s], o);
                else        buf[tid * 17 + s] += o;
            }
        }
        __syncthreads();
    }

    // stage w2 into smem (region disjoint from buf)
    float* w2s = (float*)(smem + OFF_W2);
    {
        const float4* w2v = (const float4*)w2;
        float4* w2d = (float4*)w2s;
        #pragma unroll
        for (int i = 0; i < (HID * ODIM / 4) / NTHREADS; i++)
            w2d[tid + i * NTHREADS] = w2v[tid + i * NTHREADS];
    }

    // ---- per-column final stats (threads 0..3) ----
    float* stats6 = (float*)(smem + OFF_STATS);
    if (tid < COLS_PER_CTA) {
        const float Sf = (float)S_DIM;
        float tsum    = buf[tid * 17 + 0];
        float tsumsq  = buf[tid * 17 + 1];
        float tsumabs = buf[tid * 17 + 2];
        float tmaxabs = buf[tid * 17 + 3];
        float tnan    = buf[tid * 17 + 4];
        float tuniq   = buf[tid * 17 + 5];
        float gmean = tsum / Sf;
        float var = fmaxf(tsumsq / Sf - gmean * gmean, 0.0f);
        float between = 0.0f;
        #pragma unroll
        for (int c = 0; c < NCLS; c++) {
            float cnt = g_class_counts[b * NCLS + c];
            float cm = buf[tid * 17 + 6 + c] / fmaxf(cnt, 1.0f);
            float d = cm - gmean;
            between = fmaf(cnt, d * d, between);
        }
        between /= Sf;
        stats6[tid * 6 + 0] = between / fmaxf(var, 1e-6f);
        stats6[tid * 6 + 1] = tnan / Sf;
        stats6[tid * 6 + 2] = tuniq / Sf;
        stats6[tid * 6 + 3] = var;
        stats6[tid * 6 + 4] = tsumabs / Sf;
        stats6[tid * 6 + 5] = tmaxabs;
    }
    __syncthreads();

    // ---- MLP layer 1: h = gelu_exact(stats6 @ w1 + b1), 4 cols x 64 ----
    float* hsm = (float*)(smem + OFF_H);
    if (tid < COLS_PER_CTA * HID) {
        int ch = tid >> 6, j = tid & 63;
        float acc = b1[j];
        #pragma unroll
        for (int i = 0; i < 6; i++)
            acc = fmaf(stats6[ch * 6 + i], w1[i * HID + j], acc);
        hsm[ch * HID + j] = 0.5f * acc * (1.0f + erff(acc * 0.70710678118654752f));
    }
    __syncthreads();

    // ---- MLP layer 2: out = h @ w2 + b2 (threads 0..511, one output each) ----
    if (tid < COLS_PER_CTA * ODIM) {
        int ch = tid >> 7, k = tid & 127;
        float acc = b2[k];
        #pragma unroll
        for (int j = 0; j < HID; j++)
            acc = fmaf(hsm[ch * HID + j], w2s[j * ODIM + k], acc);
        out[(((size_t)b * F_DIM) + f0 + ch) * ODIM + k] = acc;
    }
}

extern "C" void kernel_launch(void* const* d_in, const int* in_sizes, int n_in,
                              void* d_out, int out_size) {
    const float* X  = (const float*)d_in[0];
    const int*   y  = (const int*)d_in[1];
    const float* w1 = (const float*)d_in[2];
    const float* b1 = (const float*)d_in[3];
    const float* w2 = (const float*)d_in[4];
    const float* b2 = (const float*)d_in[5];
    float* out = (float*)d_out;

    cudaFuncSetAttribute(stats_mlp_kernel,
                         cudaFuncAttributeMaxDynamicSharedMemorySize, SMEM_BYTES);

    class_count_kernel<<<B_DIM, 256>>>(y);
    dim3 grid(F_DIM / COLS_PER_CTA, B_DIM);
    stats_mlp_kernel<<<grid, NTHREADS, SMEM_BYTES>>>(X, y, w1, b1, w2, b2, out);
}